// round 9
// baseline (speedup 1.0000x reference)
#include <cuda_runtime.h>
#include <cuda_bf16.h>
#include <cstdint>

#define DIM 64

// fp32 effective conv weights [tap][ci][co]
__device__ float g_W[125 * DIM * DIM];
// bf16 swizzled B slabs: [25 planes][hi 20480 | lo 20480] elems (k=320 rows x 64 n)
__device__ __align__(128) __nv_bfloat16 g_B[25 * 40960];
// channel-last bf16 split of x: [b][x][y][z][ci]
__device__ __align__(128) __nv_bfloat16 g_xhi[2ull * 64 * 64 * 64 * 64];
__device__ __align__(128) __nv_bfloat16 g_xlo[2ull * 64 * 64 * 64 * 64];
// 16B zero source for halo cp.async
__device__ __align__(16) float g_zero[4] = {0.f, 0.f, 0.f, 0.f};

// ---------------------------------------------------------------------------
// Kernel 1: effective fp32 weights (validated rounds 2-8)
// ---------------------------------------------------------------------------
__global__ void build_weights(const float* __restrict__ lw0,
                              const float* __restrict__ lw1,
                              const float* __restrict__ tp)
{
    const int t  = blockIdx.x;
    const int a  = t / 25;
    const int b2 = (t / 5) % 5;
    const int c  = t % 5;

    const float lx = -1.f + 0.5f * (float)a;
    const float ly = -1.f + 0.5f * (float)b2;
    const float lz = -1.f + 0.5f * (float)c;
    const float d  = sqrtf(lx*lx + ly*ly + lz*lz);

    float ux = 0.f, uy = 0.f, uz = 0.f;
    if (d > 0.f) { ux = lx / d; uy = ly / d; uz = lz / d; }
    const float SQ3 = 1.7320508075688772f;
    const float s0 = SQ3 * uy, s1 = SQ3 * uz, s2 = SQ3 * ux;

    const float scale = cosf(3.14159265358979323846f * d) / 11.180339887498949f;
    float coef[5];
#pragma unroll
    for (int s = 0; s < 5; s++) {
        float u = (d - 0.25f * (float)s) / 0.25f;
        coef[s] = expf(-u * u) * (1.0f / 1.12f) * scale;
    }

    float* W = g_W + t * (DIM * DIM);
    for (int i = threadIdx.x; i < DIM * DIM; i += blockDim.x) W[i] = 0.f;
    __syncthreads();

    const int u_ = threadIdx.x >> 4;
    const int w_ = threadIdx.x & 15;
    const int m  = u_ * 16 + w_;

    float eA = 0.f, eB = 0.f, eC = 0.f, eD = 0.f;
#pragma unroll
    for (int s = 0; s < 5; s++) {
        const float cs = coef[s];
        eA += cs * tp[s * 1024 +   0 + m];
        eB += cs * tp[s * 1024 + 256 + m];
        eC += cs * tp[s * 1024 + 512 + m];
        eD += cs * tp[s * 1024 + 768 + m];
    }

    const float A0  = 0.17677669529663689f;
    const float A1  = 0.30618621784789724f;
    const float IS3 = 0.57735026918962576f;
    const float inv = 0.25f;
    const bool  center = (t == 62);

    {
        float v = 0.1f * A0 * eA;
        if (center) v += inv * lw0[u_ * 16 + w_];
        W[u_ * DIM + w_] = v;
    }
    {
        const float base = 0.1f * A1 * IS3 * eB;
        W[u_ * DIM + 16 + w_ * 3 + 0] = base * s0;
        W[u_ * DIM + 16 + w_ * 3 + 1] = base * s1;
        W[u_ * DIM + 16 + w_ * 3 + 2] = base * s2;
    }
    {
        const float b10 = 0.1f * A0 * IS3 * eD;
        float v11 = 0.1f * A1 * IS3 * eC;
        if (center) v11 += inv * lw1[u_ * 16 + w_];
        const float sh[3] = { s0, s1, s2 };
#pragma unroll
        for (int i = 0; i < 3; i++) {
            W[(16 + u_ * 3 + i) * DIM + w_]              = b10 * sh[i];
            W[(16 + u_ * 3 + i) * DIM + 16 + w_ * 3 + i] = v11;
        }
    }
}

// ---------------------------------------------------------------------------
// Kernel 2: B slabs, bf16 hi/lo, rows k = c*64+ci (128B), XOR-swizzled cols
// ---------------------------------------------------------------------------
__global__ void build_B()
{
    const int t  = blockIdx.x;       // 0..124
    const int ss = t / 5;            // plane (a*5+bb)
    const int c  = t % 5;
    const float* W = g_W + t * 4096;

    __nv_bfloat16* hi = g_B + (size_t)ss * 40960;
    __nv_bfloat16* lo = hi + 20480;

    for (int idx = threadIdx.x; idx < 4096; idx += blockDim.x) {
        const int ci = idx >> 6;
        const int n  = idx & 63;
        const float v = W[ci * 64 + n];
        __nv_bfloat16 h = __float2bfloat16(v);
        __nv_bfloat16 l = __float2bfloat16(v - __bfloat162float(h));
        const int k = c * 64 + ci;
        const uint32_t off = (uint32_t)k * 128u
                           + (((uint32_t)n * 2u) ^ (((uint32_t)k & 7u) << 4));
        hi[off >> 1] = h;
        lo[off >> 1] = l;
    }
}

// ---------------------------------------------------------------------------
// Kernel 3: split + transpose x -> channel-last bf16 hi/lo
// ---------------------------------------------------------------------------
__global__ void __launch_bounds__(256) xsplit(const float* __restrict__ x)
{
    __shared__ float s[64][65];
    const int gid = blockIdx.x;            // b*4096 + xx*64 + y
    const int y  = gid & 63;
    const int xx = (gid >> 6) & 63;
    const int b  = gid >> 12;
    const int tid = threadIdx.x;
    const int zz = tid & 63;
    const int cq = tid >> 6;               // 0..3

    const size_t sp = (size_t)(xx * 64 + y) * 64;
#pragma unroll
    for (int r = 0; r < 16; r++) {
        const int ci = cq * 16 + r;
        s[ci][zz] = x[(size_t)(b * 64 + ci) * 262144 + sp + zz];
    }
    __syncthreads();

    __nv_bfloat16* oH = g_xhi + (((size_t)(b * 64 + xx) * 64 + y) << 12);
    __nv_bfloat16* oL = g_xlo + (((size_t)(b * 64 + xx) * 64 + y) << 12);
    const int ci_w = tid & 63;
#pragma unroll
    for (int r = 0; r < 16; r++) {
        const int z = cq * 16 + r;
        const float v = s[ci_w][z];
        __nv_bfloat16 h = __float2bfloat16(v);
        __nv_bfloat16 l = __float2bfloat16(v - __bfloat162float(h));
        oH[z * 64 + ci_w] = h;
        oL[z * 64 + ci_w] = l;
    }
}

// ---------------------------------------------------------------------------
// PTX helpers (all base-target sm_80+ instructions)
// ---------------------------------------------------------------------------
__device__ __forceinline__ uint32_t smem_u32(const void* p) {
    uint32_t a;
    asm("{ .reg .u64 t; cvta.to.shared.u64 t, %1; cvt.u32.u64 %0, t; }"
        : "=r"(a) : "l"(p));
    return a;
}
__device__ __forceinline__ void ldsm4(uint32_t& r0, uint32_t& r1,
                                      uint32_t& r2, uint32_t& r3, uint32_t a) {
    asm volatile("ldmatrix.sync.aligned.m8n8.x4.shared.b16 {%0,%1,%2,%3}, [%4];"
                 : "=r"(r0), "=r"(r1), "=r"(r2), "=r"(r3) : "r"(a));
}
__device__ __forceinline__ void ldsm4t(uint32_t& r0, uint32_t& r1,
                                       uint32_t& r2, uint32_t& r3, uint32_t a) {
    asm volatile("ldmatrix.sync.aligned.m8n8.x4.trans.shared.b16 {%0,%1,%2,%3}, [%4];"
                 : "=r"(r0), "=r"(r1), "=r"(r2), "=r"(r3) : "r"(a));
}
__device__ __forceinline__ void mma16816(float* d, uint32_t a0, uint32_t a1,
                                         uint32_t a2, uint32_t a3,
                                         uint32_t b0, uint32_t b1) {
    asm volatile(
        "mma.sync.aligned.m16n8k16.row.col.f32.bf16.bf16.f32 "
        "{%0,%1,%2,%3}, {%4,%5,%6,%7}, {%8,%9}, {%0,%1,%2,%3};"
        : "+f"(d[0]), "+f"(d[1]), "+f"(d[2]), "+f"(d[3])
        : "r"(a0), "r"(a1), "r"(a2), "r"(a3), "r"(b0), "r"(b1));
}
__device__ __forceinline__ void cpa16(uint32_t dst, const void* src) {
    asm volatile("cp.async.cg.shared.global [%0], [%1], 16;"
                 :: "r"(dst), "l"(src));
}
#define CP_COMMIT() asm volatile("cp.async.commit_group;" ::: "memory")
#define CP_WAIT0()  asm volatile("cp.async.wait_group 0;" ::: "memory")

// ---------------------------------------------------------------------------
// SMEM map (bytes, within dynamic smem)
// ---------------------------------------------------------------------------
#define SM_B    0
#define SM_IN   163840
#define SM_ZERO 229376
#define SM_TOT  229504

// ---------------------------------------------------------------------------
// Kernel 4: mma.sync implicit-GEMM conv, double-buffered, warp tile m32n64
//   CTA = (b, x0, y0 pair). M=128 (2y x 64z), N=64, 25 (a,bb) planes.
//   128 threads = 4 warps; warp w: ysw = w>>1, z range [(w&1)*32, +32)
// ---------------------------------------------------------------------------
__global__ void __launch_bounds__(128, 1)
conv_mma(float* __restrict__ out)
{
    extern __shared__ char smem[];
    const uint32_t sb = smem_u32(smem);
    const int tid  = threadIdx.x;
    const int wid  = tid >> 5;
    const int lane = tid & 31;

    const int gid = blockIdx.x;
    const int y0  = (gid & 31) * 2;
    const int x0  = (gid >> 5) & 63;
    const int b   = gid >> 11;

    // init shared zero halo row (used by out-of-range ldmatrix lanes)
    if (tid < 8)
        *(float4*)(smem + SM_ZERO + tid * 16) = make_float4(0.f, 0.f, 0.f, 0.f);

    // plane list (uniform across block)
    int pslab[25], pxi[25], pbb[25];
    int npl = 0;
#pragma unroll
    for (int a = 0; a < 5; a++) {
        const int xi = x0 + a - 2;
        if ((unsigned)xi >= 64u) continue;
#pragma unroll
        for (int bb = 0; bb < 5; bb++) {
            const int yi0 = y0 + bb - 2;
            const int yi1 = yi0 + 1;
            if ((unsigned)yi0 >= 64u && (unsigned)yi1 >= 64u) continue;
            pslab[npl] = a * 5 + bb;
            pxi[npl]   = xi;
            pbb[npl]   = bb;
            npl++;
        }
    }

    // per-warp / per-thread constants
    const int zb   = (wid & 1) * 32;                 // z base of this warp's m32
    const int ysw  = wid >> 1;                       // ys of this warp
    const int mloc = (lane & 7) + ((lane >> 3) & 1) * 8;
    const int ksub = lane >> 4;                      // 0/1 -> +16B column
    const uint32_t zeroAddr = sb + SM_ZERO;
    float acc[2][8][4];
#pragma unroll
    for (int mt = 0; mt < 2; mt++)
#pragma unroll
        for (int nt = 0; nt < 8; nt++)
#pragma unroll
            for (int i = 0; i < 4; i++) acc[mt][nt][i] = 0.f;

    // staging lambdas -------------------------------------------------------
    auto stage_B = [&](int p, int buf) {
        const __nv_bfloat16* src = g_B + (size_t)pslab[p] * 40960;
        const uint32_t dst0 = sb + SM_B + buf * 81920;
#pragma unroll
        for (int i = 0; i < 40; i++) {
            const int id = tid + i * 128;            // 0..5119
            cpa16(dst0 + id * 16, src + id * 8);
        }
    };
    auto stage_In = [&](int p, int stg) {
        const int xi = pxi[p], bb = pbb[p];
#pragma unroll
        for (int i = 0; i < 16; i++) {
            const int id   = tid + i * 128;          // 0..2047
            const int col  = id & 7;
            const int z    = (id >> 3) & 63;
            const int half = (id >> 9) & 1;
            const int ys   = id >> 10;
            const int yi   = y0 + ys + bb - 2;
            const bool ok  = (unsigned)yi < 64u;
            const __nv_bfloat16* g = half ? g_xlo : g_xhi;
            const void* src = ok
                ? (const void*)(g + (((size_t)(b * 64 + xi) * 64 + yi) << 12)
                                + z * 64 + col * 8)
                : (const void*)g_zero;
            const uint32_t dst = sb + SM_IN + stg * 32768
                               + (ys * 2 + half) * 8192 + z * 128
                               + (((uint32_t)col * 16u) ^ (((uint32_t)z & 7u) << 4));
            cpa16(dst, src);
        }
    };

    // prologue
    stage_B(0, 0);
    stage_In(0, 0);
    CP_COMMIT();
    CP_WAIT0();
    __syncthreads();

#pragma unroll 1
    for (int p = 0; p < npl; p++) {
        // prefetch next plane into the other buffers (fully overlapped)
        if (p + 1 < npl) {
            stage_B(p + 1, (p + 1) & 1);
            stage_In(p + 1, (p + 1) & 1);
            CP_COMMIT();
        }

        const uint32_t bbH = sb + SM_B + (p & 1) * 81920;
        const uint32_t bbL = bbH + 40960;
        const uint32_t inH = sb + SM_IN + (p & 1) * 32768 + ysw * 16384;
        const uint32_t inL = inH + 8192;

        // ---- compute: 5 c-taps x 4 ci-blocks of k16, m32n64 per warp ----
#pragma unroll 1
        for (int c = 0; c < 5; c++) {
            const int zr = zb + mloc + c - 2;        // input z row, mt=0
#pragma unroll
            for (int q = 0; q < 4; q++) {            // ci0 = q*16
                // B fragments for this k16 row, all 8 n-tiles, hi+lo
                const int krow = c * 64 + q * 16 + mloc;
                const uint32_t kx = ((uint32_t)krow & 7u) << 4;
                const uint32_t brow = (uint32_t)krow * 128u;
                uint32_t bh[4][4], bl[4][4];
#pragma unroll
                for (int nq = 0; nq < 4; nq++) {
                    const uint32_t bcol = ((uint32_t)(nq * 32 + ksub * 16)) ^ kx;
                    ldsm4t(bh[nq][0], bh[nq][1], bh[nq][2], bh[nq][3],
                           bbH + brow + bcol);
                    ldsm4t(bl[nq][0], bl[nq][1], bl[nq][2], bl[nq][3],
                           bbL + brow + bcol);
                }
                // A fragments for both m16 tiles, hi+lo
                uint32_t ah[2][4], al[2][4];
#pragma unroll
                for (int mt = 0; mt < 2; mt++) {
                    const int zi = zr + mt * 16;
                    const bool vz = (unsigned)zi < 64u;
                    const uint32_t jx   = ((uint32_t)zi & 7u) << 4;
                    const uint32_t arow = (uint32_t)zi * 128u;
                    const uint32_t acol = ((uint32_t)(q * 32 + ksub * 16)) ^ jx;
                    const uint32_t aH = vz ? (inH + arow + acol) : zeroAddr;
                    const uint32_t aL = vz ? (inL + arow + acol) : zeroAddr;
                    ldsm4(ah[mt][0], ah[mt][1], ah[mt][2], ah[mt][3], aH);
                    ldsm4(al[mt][0], al[mt][1], al[mt][2], al[mt][3], aL);
                }
                // 48 MMAs
#pragma unroll
                for (int mt = 0; mt < 2; mt++) {
#pragma unroll
                    for (int nq = 0; nq < 4; nq++) {
                        float* d0 = acc[mt][2 * nq];
                        float* d1 = acc[mt][2 * nq + 1];
                        mma16816(d0, ah[mt][0], ah[mt][1], ah[mt][2], ah[mt][3],
                                 bh[nq][0], bh[nq][1]);
                        mma16816(d1, ah[mt][0], ah[mt][1], ah[mt][2], ah[mt][3],
                                 bh[nq][2], bh[nq][3]);
                        mma16816(d0, al[mt][0], al[mt][1], al[mt][2], al[mt][3],
                                 bh[nq][0], bh[nq][1]);
                        mma16816(d1, al[mt][0], al[mt][1], al[mt][2], al[mt][3],
                                 bh[nq][2], bh[nq][3]);
                        mma16816(d0, ah[mt][0], ah[mt][1], ah[mt][2], ah[mt][3],
                                 bl[nq][0], bl[nq][1]);
                        mma16816(d1, ah[mt][0], ah[mt][1], ah[mt][2], ah[mt][3],
                                 bl[nq][2], bl[nq][3]);
                    }
                }
            }
        }

        if (p + 1 < npl) CP_WAIT0();   // copies have had the whole compute to land
        __syncthreads();               // all warps done reading bufs p; bufs p+1 ready
    }

    // ---- epilogue: direct global stores ----
    const int g  = lane >> 2;
    const int cc = lane & 3;
    const int y  = y0 + ysw;
#pragma unroll
    for (int mt = 0; mt < 2; mt++) {
        const int z = zb + mt * 16 + g;
        float* ob = out + ((((size_t)b * 64) * 64 + x0) * 64 + y) * 64 + z;
#pragma unroll
        for (int nt = 0; nt < 8; nt++) {
            const int n = nt * 8 + 2 * cc;
            float* p0 = ob + (size_t)n * 262144;
            float* p1 = ob + (size_t)(n + 1) * 262144;
            p0[0] = acc[mt][nt][0];
            p1[0] = acc[mt][nt][1];
            p0[8] = acc[mt][nt][2];
            p1[8] = acc[mt][nt][3];
        }
    }
}

// ---------------------------------------------------------------------------
// Launch
// ---------------------------------------------------------------------------
extern "C" void kernel_launch(void* const* d_in, const int* in_sizes, int n_in,
                              void* d_out, int out_size)
{
    const float* x   = (const float*)d_in[0];
    const float* lw0 = (const float*)d_in[1];
    const float* lw1 = (const float*)d_in[2];
    const float* tp  = (const float*)d_in[3];
    float* out = (float*)d_out;

    xsplit<<<2 * 64 * 64, 256>>>(x);
    build_weights<<<125, 256>>>(lw0, lw1, tp);
    build_B<<<125, 256>>>();

    cudaFuncSetAttribute(conv_mma, cudaFuncAttributeMaxDynamicSharedMemorySize,
                         SM_TOT);
    conv_mma<<<2 * 64 * 32, 128, SM_TOT>>>(out);
}

// round 10
// speedup vs baseline: 1.4133x; 1.4133x over previous
#include <cuda_runtime.h>
#include <cuda_bf16.h>
#include <cstdint>

#define DIM 64

// fp32 effective conv weights [tap][ci][co]  (ORIGINAL channel order)
__device__ float g_W[125 * DIM * DIM];
// bf16 swizzled B slabs: [25 planes][hi 20480 | lo 20480] elems (k=320 x n=64, PERMUTED channels)
__device__ __align__(128) __nv_bfloat16 g_B[25 * 40960];
// channel-last bf16 split of x: [b][x][y][z][ci']  (PERMUTED channels)
__device__ __align__(128) __nv_bfloat16 g_xhi[2ull * 64 * 64 * 64 * 64];
__device__ __align__(128) __nv_bfloat16 g_xlo[2ull * 64 * 64 * 64 * 64];
// 16B zero source for halo cp.async
__device__ __align__(16) float g_zero[4] = {0.f, 0.f, 0.f, 0.f};

// channel permutation: orig 16+3u+i  ->  16+16i+u ; identity below 16
__device__ __forceinline__ int perm_ch(int ci) {
    if (ci < 16) return ci;
    const int r = ci - 16;
    return 16 + (r % 3) * 16 + (r / 3);
}
__device__ __forceinline__ int unperm_ch(int cp) {
    if (cp < 16) return cp;
    const int r = cp - 16;
    return 16 + 3 * (r & 15) + (r >> 4);
}

// ---------------------------------------------------------------------------
// Kernel 1: effective fp32 weights (validated rounds 2-9)
// ---------------------------------------------------------------------------
__global__ void build_weights(const float* __restrict__ lw0,
                              const float* __restrict__ lw1,
                              const float* __restrict__ tp)
{
    const int t  = blockIdx.x;
    const int a  = t / 25;
    const int b2 = (t / 5) % 5;
    const int c  = t % 5;

    const float lx = -1.f + 0.5f * (float)a;
    const float ly = -1.f + 0.5f * (float)b2;
    const float lz = -1.f + 0.5f * (float)c;
    const float d  = sqrtf(lx*lx + ly*ly + lz*lz);

    float ux = 0.f, uy = 0.f, uz = 0.f;
    if (d > 0.f) { ux = lx / d; uy = ly / d; uz = lz / d; }
    const float SQ3 = 1.7320508075688772f;
    const float s0 = SQ3 * uy, s1 = SQ3 * uz, s2 = SQ3 * ux;

    const float scale = cosf(3.14159265358979323846f * d) / 11.180339887498949f;
    float coef[5];
#pragma unroll
    for (int s = 0; s < 5; s++) {
        float u = (d - 0.25f * (float)s) / 0.25f;
        coef[s] = expf(-u * u) * (1.0f / 1.12f) * scale;
    }

    float* W = g_W + t * (DIM * DIM);
    for (int i = threadIdx.x; i < DIM * DIM; i += blockDim.x) W[i] = 0.f;
    __syncthreads();

    const int u_ = threadIdx.x >> 4;
    const int w_ = threadIdx.x & 15;
    const int m  = u_ * 16 + w_;

    float eA = 0.f, eB = 0.f, eC = 0.f, eD = 0.f;
#pragma unroll
    for (int s = 0; s < 5; s++) {
        const float cs = coef[s];
        eA += cs * tp[s * 1024 +   0 + m];
        eB += cs * tp[s * 1024 + 256 + m];
        eC += cs * tp[s * 1024 + 512 + m];
        eD += cs * tp[s * 1024 + 768 + m];
    }

    const float A0  = 0.17677669529663689f;
    const float A1  = 0.30618621784789724f;
    const float IS3 = 0.57735026918962576f;
    const float inv = 0.25f;
    const bool  center = (t == 62);

    {
        float v = 0.1f * A0 * eA;
        if (center) v += inv * lw0[u_ * 16 + w_];
        W[u_ * DIM + w_] = v;
    }
    {
        const float base = 0.1f * A1 * IS3 * eB;
        W[u_ * DIM + 16 + w_ * 3 + 0] = base * s0;
        W[u_ * DIM + 16 + w_ * 3 + 1] = base * s1;
        W[u_ * DIM + 16 + w_ * 3 + 2] = base * s2;
    }
    {
        const float b10 = 0.1f * A0 * IS3 * eD;
        float v11 = 0.1f * A1 * IS3 * eC;
        if (center) v11 += inv * lw1[u_ * 16 + w_];
        const float sh[3] = { s0, s1, s2 };
#pragma unroll
        for (int i = 0; i < 3; i++) {
            W[(16 + u_ * 3 + i) * DIM + w_]              = b10 * sh[i];
            W[(16 + u_ * 3 + i) * DIM + 16 + w_ * 3 + i] = v11;
        }
    }
}

// ---------------------------------------------------------------------------
// Kernel 2: B slabs, bf16 hi/lo, rows k = c*64+ci' (128B), XOR-swizzled,
//           PERMUTED channel order on both k (ci) and n (cout)
// ---------------------------------------------------------------------------
__global__ void build_B()
{
    const int t  = blockIdx.x;       // 0..124
    const int ss = t / 5;            // plane (a*5+bb)
    const int c  = t % 5;
    const float* W = g_W + t * 4096;

    __nv_bfloat16* hi = g_B + (size_t)ss * 40960;
    __nv_bfloat16* lo = hi + 20480;

    for (int idx = threadIdx.x; idx < 4096; idx += blockDim.x) {
        const int cip = idx >> 6;         // permuted ci
        const int np  = idx & 63;         // permuted cout
        const float v = W[unperm_ch(cip) * 64 + unperm_ch(np)];
        __nv_bfloat16 h = __float2bfloat16(v);
        __nv_bfloat16 l = __float2bfloat16(v - __bfloat162float(h));
        const int k = c * 64 + cip;
        const uint32_t off = (uint32_t)k * 128u
                           + (((uint32_t)np * 2u) ^ (((uint32_t)k & 7u) << 4));
        hi[off >> 1] = h;
        lo[off >> 1] = l;
    }
}

// ---------------------------------------------------------------------------
// Kernel 3: split + transpose x -> channel-last (PERMUTED) bf16 hi/lo
// ---------------------------------------------------------------------------
__global__ void __launch_bounds__(256) xsplit(const float* __restrict__ x)
{
    __shared__ float s[64][65];
    const int gid = blockIdx.x;            // b*4096 + xx*64 + y
    const int y  = gid & 63;
    const int xx = (gid >> 6) & 63;
    const int b  = gid >> 12;
    const int tid = threadIdx.x;
    const int zz = tid & 63;
    const int cq = tid >> 6;               // 0..3

    const size_t sp = (size_t)(xx * 64 + y) * 64;
#pragma unroll
    for (int r = 0; r < 16; r++) {
        const int ci = cq * 16 + r;
        s[ci][zz] = x[(size_t)(b * 64 + ci) * 262144 + sp + zz];
    }
    __syncthreads();

    __nv_bfloat16* oH = g_xhi + (((size_t)(b * 64 + xx) * 64 + y) << 12);
    __nv_bfloat16* oL = g_xlo + (((size_t)(b * 64 + xx) * 64 + y) << 12);
    const int ci_w = tid & 63;
    const int cp   = perm_ch(ci_w);
#pragma unroll
    for (int r = 0; r < 16; r++) {
        const int z = cq * 16 + r;
        const float v = s[ci_w][z];
        __nv_bfloat16 h = __float2bfloat16(v);
        __nv_bfloat16 l = __float2bfloat16(v - __bfloat162float(h));
        oH[z * 64 + cp] = h;
        oL[z * 64 + cp] = l;
    }
}

// ---------------------------------------------------------------------------
// PTX helpers (all base-target sm_80+ instructions)
// ---------------------------------------------------------------------------
__device__ __forceinline__ uint32_t smem_u32(const void* p) {
    uint32_t a;
    asm("{ .reg .u64 t; cvta.to.shared.u64 t, %1; cvt.u32.u64 %0, t; }"
        : "=r"(a) : "l"(p));
    return a;
}
__device__ __forceinline__ void ldsm4(uint32_t& r0, uint32_t& r1,
                                      uint32_t& r2, uint32_t& r3, uint32_t a) {
    asm volatile("ldmatrix.sync.aligned.m8n8.x4.shared.b16 {%0,%1,%2,%3}, [%4];"
                 : "=r"(r0), "=r"(r1), "=r"(r2), "=r"(r3) : "r"(a));
}
__device__ __forceinline__ void ldsm4t(uint32_t& r0, uint32_t& r1,
                                       uint32_t& r2, uint32_t& r3, uint32_t a) {
    asm volatile("ldmatrix.sync.aligned.m8n8.x4.trans.shared.b16 {%0,%1,%2,%3}, [%4];"
                 : "=r"(r0), "=r"(r1), "=r"(r2), "=r"(r3) : "r"(a));
}
__device__ __forceinline__ void mma16816(float* d, uint32_t a0, uint32_t a1,
                                         uint32_t a2, uint32_t a3,
                                         uint32_t b0, uint32_t b1) {
    asm volatile(
        "mma.sync.aligned.m16n8k16.row.col.f32.bf16.bf16.f32 "
        "{%0,%1,%2,%3}, {%4,%5,%6,%7}, {%8,%9}, {%0,%1,%2,%3};"
        : "+f"(d[0]), "+f"(d[1]), "+f"(d[2]), "+f"(d[3])
        : "r"(a0), "r"(a1), "r"(a2), "r"(a3), "r"(b0), "r"(b1));
}
__device__ __forceinline__ void cpa16(uint32_t dst, const void* src) {
    asm volatile("cp.async.cg.shared.global [%0], [%1], 16;"
                 :: "r"(dst), "l"(src));
}
#define CP_COMMIT() asm volatile("cp.async.commit_group;" ::: "memory")
#define CP_WAIT0()  asm volatile("cp.async.wait_group 0;" ::: "memory")

// ---------------------------------------------------------------------------
// SMEM map (bytes, within dynamic smem)
// ---------------------------------------------------------------------------
#define SM_B    0
#define SM_IN   163840
#define SM_ZERO 229376
#define SM_TOT  229504

// ---------------------------------------------------------------------------
// Kernel 4: mma.sync implicit-GEMM conv, double-buffered (R8 config),
//           block-sparse skip: (q>=1 && nq>=1 && q!=nq) blocks are zero.
//   CTA = (b, x0, y0 pair). M=128 (2y x 64z), N=64, 25 (a,bb) planes.
// ---------------------------------------------------------------------------
__global__ void __launch_bounds__(256, 1)
conv_mma(float* __restrict__ out)
{
    extern __shared__ char smem[];
    const uint32_t sb = smem_u32(smem);
    const int tid  = threadIdx.x;
    const int wid  = tid >> 5;
    const int lane = tid & 31;

    const int gid = blockIdx.x;
    const int y0  = (gid & 31) * 2;
    const int x0  = (gid >> 5) & 63;
    const int b   = gid >> 11;

    // init shared zero halo row (used by out-of-range ldmatrix lanes)
    if (tid < 8)
        *(float4*)(smem + SM_ZERO + tid * 16) = make_float4(0.f, 0.f, 0.f, 0.f);

    // plane list (uniform across block)
    int pslab[25], pxi[25], pbb[25];
    int npl = 0;
#pragma unroll
    for (int a = 0; a < 5; a++) {
        const int xi = x0 + a - 2;
        if ((unsigned)xi >= 64u) continue;
#pragma unroll
        for (int bb = 0; bb < 5; bb++) {
            const int yi0 = y0 + bb - 2;
            const int yi1 = yi0 + 1;
            if ((unsigned)yi0 >= 64u && (unsigned)yi1 >= 64u) continue;
            pslab[npl] = a * 5 + bb;
            pxi[npl]   = xi;
            pbb[npl]   = bb;
            npl++;
        }
    }

    // per-warp / per-thread constants
    const int zb   = (wid & 3) * 16;                 // z base of this warp's m16
    const int ysw  = wid >> 2;                       // ys of this warp
    const int mloc = (lane & 7) + ((lane >> 3) & 1) * 8;
    const int ksub = lane >> 4;                      // 0/1 -> +16B column
    const uint32_t zeroAddr = sb + SM_ZERO;
    float acc[8][4];
#pragma unroll
    for (int nt = 0; nt < 8; nt++)
#pragma unroll
        for (int i = 0; i < 4; i++) acc[nt][i] = 0.f;

    // staging lambdas -------------------------------------------------------
    auto stage_B = [&](int p, int buf) {
        const __nv_bfloat16* src = g_B + (size_t)pslab[p] * 40960;
        const uint32_t dst0 = sb + SM_B + buf * 81920;
#pragma unroll
        for (int i = 0; i < 20; i++) {
            const int id = tid + i * 256;            // 0..5119
            cpa16(dst0 + id * 16, src + id * 8);
        }
    };
    auto stage_In = [&](int p, int stg) {
        const int xi = pxi[p], bb = pbb[p];
#pragma unroll
        for (int i = 0; i < 8; i++) {
            const int id   = tid + i * 256;          // 0..2047
            const int col  = id & 7;
            const int z    = (id >> 3) & 63;
            const int half = (id >> 9) & 1;
            const int ys   = id >> 10;
            const int yi   = y0 + ys + bb - 2;
            const bool ok  = (unsigned)yi < 64u;
            const __nv_bfloat16* g = half ? g_xlo : g_xhi;
            const void* src = ok
                ? (const void*)(g + (((size_t)(b * 64 + xi) * 64 + yi) << 12)
                                + z * 64 + col * 8)
                : (const void*)g_zero;
            const uint32_t dst = sb + SM_IN + stg * 32768
                               + (ys * 2 + half) * 8192 + z * 128
                               + (((uint32_t)col * 16u) ^ (((uint32_t)z & 7u) << 4));
            cpa16(dst, src);
        }
    };

    // prologue
    stage_B(0, 0);
    stage_In(0, 0);
    CP_COMMIT();
    CP_WAIT0();
    __syncthreads();

#pragma unroll 1
    for (int p = 0; p < npl; p++) {
        // prefetch next plane into the other buffers (fully overlapped)
        if (p + 1 < npl) {
            stage_B(p + 1, (p + 1) & 1);
            stage_In(p + 1, (p + 1) & 1);
            CP_COMMIT();
        }

        const uint32_t bbH = sb + SM_B + (p & 1) * 81920;
        const uint32_t bbL = bbH + 40960;
        const uint32_t inH = sb + SM_IN + (p & 1) * 32768 + ysw * 16384;
        const uint32_t inL = inH + 8192;

        // ---- compute: 5 c-taps x 4 ci-blocks, sparse (q,nq) pattern ----
#pragma unroll 1
        for (int c = 0; c < 5; c++) {
            const int zi = zb + mloc + c - 2;        // input z row (per lane)
            const bool vz = (unsigned)zi < 64u;
            const uint32_t jx   = ((uint32_t)zi & 7u) << 4;
            const uint32_t arow = (uint32_t)zi * 128u;
#pragma unroll
            for (int q = 0; q < 4; q++) {            // ci0 = q*16 (permuted)
                const uint32_t acol = ((uint32_t)(q * 32 + ksub * 16)) ^ jx;
                const uint32_t aH = vz ? (inH + arow + acol) : zeroAddr;
                const uint32_t aL = vz ? (inL + arow + acol) : zeroAddr;
                uint32_t ah0, ah1, ah2, ah3, al0, al1, al2, al3;
                ldsm4(ah0, ah1, ah2, ah3, aH);
                ldsm4(al0, al1, al2, al3, aL);

                const int krow = c * 64 + q * 16 + mloc;
                const uint32_t kx = ((uint32_t)krow & 7u) << 4;
                const uint32_t brow = (uint32_t)krow * 128u;
#pragma unroll
                for (int nq = 0; nq < 4; nq++) {     // n0 = nq*16 (permuted)
                    if (q != 0 && nq != 0 && q != nq) continue;   // zero block
                    const uint32_t bcol = ((uint32_t)(nq * 32 + ksub * 16)) ^ kx;
                    uint32_t bh0, bh1, bh2, bh3, bl0, bl1, bl2, bl3;
                    ldsm4t(bh0, bh1, bh2, bh3, bbH + brow + bcol);
                    ldsm4t(bl0, bl1, bl2, bl3, bbL + brow + bcol);
                    float* d0 = acc[2 * nq];
                    float* d1 = acc[2 * nq + 1];
                    mma16816(d0, ah0, ah1, ah2, ah3, bh0, bh1);
                    mma16816(d1, ah0, ah1, ah2, ah3, bh2, bh3);
                    mma16816(d0, al0, al1, al2, al3, bh0, bh1);
                    mma16816(d1, al0, al1, al2, al3, bh2, bh3);
                    mma16816(d0, ah0, ah1, ah2, ah3, bl0, bl1);
                    mma16816(d1, ah0, ah1, ah2, ah3, bl2, bl3);
                }
            }
        }

        if (p + 1 < npl) CP_WAIT0();   // copies have had the whole compute to land
        __syncthreads();               // all warps done reading bufs p; bufs p+1 ready
    }

    // ---- epilogue: direct global stores, un-permute cout ----
    const int g  = lane >> 2;
    const int cc = lane & 3;
    const int z  = zb + g;
    const int y  = y0 + ysw;
    float* ob = out + ((((size_t)b * 64) * 64 + x0) * 64 + y) * 64 + z;
#pragma unroll
    for (int nt = 0; nt < 8; nt++) {
        const int n0 = nt * 8 + 2 * cc;
        const int ch0 = (n0 < 16) ? n0 : (16 + 3 * ((n0 - 16) & 15) + ((n0 - 16) >> 4));
        const int n1 = n0 + 1;
        const int ch1 = (n1 < 16) ? n1 : (16 + 3 * ((n1 - 16) & 15) + ((n1 - 16) >> 4));
        float* p0 = ob + (size_t)ch0 * 262144;
        float* p1 = ob + (size_t)ch1 * 262144;
        p0[0] = acc[nt][0];
        p1[0] = acc[nt][1];
        p0[8] = acc[nt][2];
        p1[8] = acc[nt][3];
    }
}

// ---------------------------------------------------------------------------
// Launch
// ---------------------------------------------------------------------------
extern "C" void kernel_launch(void* const* d_in, const int* in_sizes, int n_in,
                              void* d_out, int out_size)
{
    const float* x   = (const float*)d_in[0];
    const float* lw0 = (const float*)d_in[1];
    const float* lw1 = (const float*)d_in[2];
    const float* tp  = (const float*)d_in[3];
    float* out = (float*)d_out;

    xsplit<<<2 * 64 * 64, 256>>>(x);
    build_weights<<<125, 256>>>(lw0, lw1, tp);
    build_B<<<125, 256>>>();

    cudaFuncSetAttribute(conv_mma, cudaFuncAttributeMaxDynamicSharedMemorySize,
                         SM_TOT);
    conv_mma<<<2 * 64 * 32, 256, SM_TOT>>>(out);
}

// round 11
// speedup vs baseline: 1.6852x; 1.1924x over previous
#include <cuda_runtime.h>
#include <cuda_bf16.h>
#include <cstdint>

#define DIM 64

// Compact B blocks, bf16 hi/lo, built directly by build_weights:
//   [tap t=slab*5+c][blk 0..5][half hi/lo][16 rows x 48B (16 n*2B + pad)]
//   blk0=k00, blk1=base01, blk2..4=b10*sh[i], blk5=v11(diag)
__device__ __align__(16) unsigned char g_Bc[125 * 6 * 2 * 768];
// channel-last bf16 split of x: [b][x][y][z][ci']  (PERMUTED channels)
__device__ __align__(128) __nv_bfloat16 g_xhi[2ull * 64 * 64 * 64 * 64];
__device__ __align__(128) __nv_bfloat16 g_xlo[2ull * 64 * 64 * 64 * 64];
// 16B zero source for halo cp.async
__device__ __align__(16) float g_zero[4] = {0.f, 0.f, 0.f, 0.f};

// channel permutation: orig 16+3u+i  ->  16+16i+u ; identity below 16
__device__ __forceinline__ int perm_ch(int ci) {
    if (ci < 16) return ci;
    const int r = ci - 16;
    return 16 + (r % 3) * 16 + (r / 3);
}

// ---------------------------------------------------------------------------
// Kernel 1: build compact B blocks (bf16 hi/lo) straight from inputs
// ---------------------------------------------------------------------------
__global__ void build_weights(const float* __restrict__ lw0,
                              const float* __restrict__ lw1,
                              const float* __restrict__ tp)
{
    const int t  = blockIdx.x;            // 0..124, t = (a*5+bb)*5 + c
    const int a  = t / 25;
    const int b2 = (t / 5) % 5;
    const int c  = t % 5;

    const float lx = -1.f + 0.5f * (float)a;
    const float ly = -1.f + 0.5f * (float)b2;
    const float lz = -1.f + 0.5f * (float)c;
    const float d  = sqrtf(lx*lx + ly*ly + lz*lz);

    float ux = 0.f, uy = 0.f, uz = 0.f;
    if (d > 0.f) { ux = lx / d; uy = ly / d; uz = lz / d; }
    const float SQ3 = 1.7320508075688772f;
    const float s0 = SQ3 * uy, s1 = SQ3 * uz, s2 = SQ3 * ux;

    const float scale = cosf(3.14159265358979323846f * d) / 11.180339887498949f;
    float coef[5];
#pragma unroll
    for (int s = 0; s < 5; s++) {
        float u = (d - 0.25f * (float)s) / 0.25f;
        coef[s] = expf(-u * u) * (1.0f / 1.12f) * scale;
    }

    const int u_ = threadIdx.x >> 4;
    const int w_ = threadIdx.x & 15;
    const int m  = u_ * 16 + w_;

    float eA = 0.f, eB = 0.f, eC = 0.f, eD = 0.f;
#pragma unroll
    for (int s = 0; s < 5; s++) {
        const float cs = coef[s];
        eA += cs * tp[s * 1024 +   0 + m];
        eB += cs * tp[s * 1024 + 256 + m];
        eC += cs * tp[s * 1024 + 512 + m];
        eD += cs * tp[s * 1024 + 768 + m];
    }

    const float A0  = 0.17677669529663689f;   // sqrt(1/32)
    const float A1  = 0.30618621784789724f;   // sqrt(3/32)
    const float IS3 = 0.57735026918962576f;   // 1/sqrt(3)
    const float inv = 0.25f;
    const bool  center = (t == 62);           // (2,2,2)
    const float b10 = 0.1f * A0 * IS3 * eD;

    float blkv[6];
    blkv[0] = 0.1f * A0 * eA + (center ? inv * lw0[m] : 0.f);
    blkv[1] = 0.1f * A1 * IS3 * eB;
    blkv[2] = b10 * s0;
    blkv[3] = b10 * s1;
    blkv[4] = b10 * s2;
    blkv[5] = 0.1f * A1 * IS3 * eC + (center ? inv * lw1[m] : 0.f);

#pragma unroll
    for (int blk = 0; blk < 6; blk++) {
        const float v = blkv[blk];
        const __nv_bfloat16 h = __float2bfloat16(v);
        const __nv_bfloat16 l = __float2bfloat16(v - __bfloat162float(h));
        const size_t off = ((size_t)(t * 6 + blk) * 2) * 768
                         + (size_t)u_ * 48 + (size_t)w_ * 2;
        *(__nv_bfloat16*)(g_Bc + off)       = h;
        *(__nv_bfloat16*)(g_Bc + off + 768) = l;
    }
}

// ---------------------------------------------------------------------------
// Kernel 2: split + transpose x -> channel-last (PERMUTED) bf16 hi/lo
// ---------------------------------------------------------------------------
__global__ void __launch_bounds__(256) xsplit(const float* __restrict__ x)
{
    __shared__ float s[64][65];
    const int gid = blockIdx.x;            // b*4096 + xx*64 + y
    const int y  = gid & 63;
    const int xx = (gid >> 6) & 63;
    const int b  = gid >> 12;
    const int tid = threadIdx.x;
    const int zz = tid & 63;
    const int cq = tid >> 6;               // 0..3

    const size_t sp = (size_t)(xx * 64 + y) * 64;
#pragma unroll
    for (int r = 0; r < 16; r++) {
        const int ci = cq * 16 + r;
        s[ci][zz] = x[(size_t)(b * 64 + ci) * 262144 + sp + zz];
    }
    __syncthreads();

    __nv_bfloat16* oH = g_xhi + (((size_t)(b * 64 + xx) * 64 + y) << 12);
    __nv_bfloat16* oL = g_xlo + (((size_t)(b * 64 + xx) * 64 + y) << 12);
    const int ci_w = tid & 63;
    const int cp   = perm_ch(ci_w);
#pragma unroll
    for (int r = 0; r < 16; r++) {
        const int z = cq * 16 + r;
        const float v = s[ci_w][z];
        __nv_bfloat16 h = __float2bfloat16(v);
        __nv_bfloat16 l = __float2bfloat16(v - __bfloat162float(h));
        oH[z * 64 + cp] = h;
        oL[z * 64 + cp] = l;
    }
}

// ---------------------------------------------------------------------------
// PTX helpers (all base-target sm_80+ instructions)
// ---------------------------------------------------------------------------
__device__ __forceinline__ uint32_t smem_u32(const void* p) {
    uint32_t a;
    asm("{ .reg .u64 t; cvta.to.shared.u64 t, %1; cvt.u32.u64 %0, t; }"
        : "=r"(a) : "l"(p));
    return a;
}
__device__ __forceinline__ void ldsm4(uint32_t& r0, uint32_t& r1,
                                      uint32_t& r2, uint32_t& r3, uint32_t a) {
    asm volatile("ldmatrix.sync.aligned.m8n8.x4.shared.b16 {%0,%1,%2,%3}, [%4];"
                 : "=r"(r0), "=r"(r1), "=r"(r2), "=r"(r3) : "r"(a));
}
__device__ __forceinline__ void ldsm4t(uint32_t& r0, uint32_t& r1,
                                       uint32_t& r2, uint32_t& r3, uint32_t a) {
    asm volatile("ldmatrix.sync.aligned.m8n8.x4.trans.shared.b16 {%0,%1,%2,%3}, [%4];"
                 : "=r"(r0), "=r"(r1), "=r"(r2), "=r"(r3) : "r"(a));
}
__device__ __forceinline__ void mma16816(float* d, uint32_t a0, uint32_t a1,
                                         uint32_t a2, uint32_t a3,
                                         uint32_t b0, uint32_t b1) {
    asm volatile(
        "mma.sync.aligned.m16n8k16.row.col.f32.bf16.bf16.f32 "
        "{%0,%1,%2,%3}, {%4,%5,%6,%7}, {%8,%9}, {%0,%1,%2,%3};"
        : "+f"(d[0]), "+f"(d[1]), "+f"(d[2]), "+f"(d[3])
        : "r"(a0), "r"(a1), "r"(a2), "r"(a3), "r"(b0), "r"(b1));
}
__device__ __forceinline__ void cpa16(uint32_t dst, const void* src) {
    asm volatile("cp.async.cg.shared.global [%0], [%1], 16;"
                 :: "r"(dst), "l"(src));
}
#define CP_COMMIT() asm volatile("cp.async.commit_group;" ::: "memory")
#define CP_WAIT0()  asm volatile("cp.async.wait_group 0;" ::: "memory")

// ---------------------------------------------------------------------------
// SMEM map (bytes, within dynamic smem)
//   B: 2 bufs x 46080 (5c x 6blk x 2half x 768B)    = 92160
//   Input: 2 stages x 4 (ys,half) x 64 rows x 128B  = 65536
// ---------------------------------------------------------------------------
#define SM_B     0
#define SM_IN    92160
#define SM_ZERO  157696
#define SM_TOT   157824
#define PLANE_B  46080

// ---------------------------------------------------------------------------
// Kernel 3: mma.sync implicit-GEMM conv, compact-block structured B
//   per c-tap: blk0 (k00) + blk1->P (k01 rank-1) + blk2..4 (k10) + blk5 (diag)
// ---------------------------------------------------------------------------
__global__ void __launch_bounds__(256, 1)
conv_mma(float* __restrict__ out)
{
    extern __shared__ char smem[];
    const uint32_t sb = smem_u32(smem);
    const int tid  = threadIdx.x;
    const int wid  = tid >> 5;
    const int lane = tid & 31;

    const int gid = blockIdx.x;
    const int y0  = (gid & 31) * 2;
    const int x0  = (gid >> 5) & 63;
    const int b   = gid >> 11;

    if (tid < 8)
        *(float4*)(smem + SM_ZERO + tid * 16) = make_float4(0.f, 0.f, 0.f, 0.f);

    // plane list (uniform across block)
    int pslab[25], pxi[25], pbb[25];
    int npl = 0;
#pragma unroll
    for (int a = 0; a < 5; a++) {
        const int xi = x0 + a - 2;
        if ((unsigned)xi >= 64u) continue;
#pragma unroll
        for (int bb = 0; bb < 5; bb++) {
            const int yi0 = y0 + bb - 2;
            const int yi1 = yi0 + 1;
            if ((unsigned)yi0 >= 64u && (unsigned)yi1 >= 64u) continue;
            pslab[npl] = a * 5 + bb;
            pxi[npl]   = xi;
            pbb[npl]   = bb;
            npl++;
        }
    }

    // per-warp / per-thread constants
    const int zb   = (wid & 3) * 16;                 // z base of this warp's m16
    const int ysw  = wid >> 2;                       // ys of this warp
    const int mloc = (lane & 7) + ((lane >> 3) & 1) * 8;
    const int ksub = lane >> 4;                      // 0/1 -> +16B column
    const uint32_t zeroAddr = sb + SM_ZERO;
    const uint32_t bl_off = (uint32_t)(lane & 15) * 48u + (uint32_t)(lane >> 4) * 16u;
    float acc[8][4];
#pragma unroll
    for (int nt = 0; nt < 8; nt++)
#pragma unroll
        for (int i = 0; i < 4; i++) acc[nt][i] = 0.f;

    // staging lambdas -------------------------------------------------------
    auto stage_B = [&](int p, int buf) {
        const unsigned char* src = g_Bc + (size_t)pslab[p] * PLANE_B;
        const uint32_t dst0 = sb + SM_B + buf * PLANE_B;
#pragma unroll
        for (int i = 0; i < 12; i++) {
            const int id = tid + i * 256;            // 0..3071
            if (id < PLANE_B / 16)
                cpa16(dst0 + id * 16, src + id * 16);
        }
    };
    auto stage_In = [&](int p, int stg) {
        const int xi = pxi[p], bb = pbb[p];
#pragma unroll
        for (int i = 0; i < 8; i++) {
            const int id   = tid + i * 256;          // 0..2047
            const int col  = id & 7;
            const int z    = (id >> 3) & 63;
            const int half = (id >> 9) & 1;
            const int ys   = id >> 10;
            const int yi   = y0 + ys + bb - 2;
            const bool ok  = (unsigned)yi < 64u;
            const __nv_bfloat16* g = half ? g_xlo : g_xhi;
            const void* src = ok
                ? (const void*)(g + (((size_t)(b * 64 + xi) * 64 + yi) << 12)
                                + z * 64 + col * 8)
                : (const void*)g_zero;
            const uint32_t dst = sb + SM_IN + stg * 32768
                               + (ys * 2 + half) * 8192 + z * 128
                               + (((uint32_t)col * 16u) ^ (((uint32_t)z & 7u) << 4));
            cpa16(dst, src);
        }
    };

    // prologue
    stage_B(0, 0);
    stage_In(0, 0);
    CP_COMMIT();
    CP_WAIT0();
    __syncthreads();

#pragma unroll 1
    for (int p = 0; p < npl; p++) {
        if (p + 1 < npl) {
            stage_B(p + 1, (p + 1) & 1);
            stage_In(p + 1, (p + 1) & 1);
            CP_COMMIT();
        }

        const uint32_t Bb  = sb + SM_B + (p & 1) * PLANE_B;
        const uint32_t inH = sb + SM_IN + (p & 1) * 32768 + ysw * 16384;
        const uint32_t inL = inH + 8192;

        const int slab = pslab[p];
        const int pa   = slab / 5;
        const int pb   = slab - pa * 5;
        const float lx = -1.f + 0.5f * (float)pa;
        const float ly = -1.f + 0.5f * (float)pb;

        // ---- compute: 5 c-taps, structured blocks ----
#pragma unroll 1
        for (int c = 0; c < 5; c++) {
            // sh1 values for this tap
            const float lz = -1.f + 0.5f * (float)c;
            const float d2 = lx*lx + ly*ly + lz*lz;
            float s[3];
            if (d2 > 0.f) {
                const float ri = rsqrtf(d2) * 1.7320508075688772f;
                s[0] = ly * ri; s[1] = lz * ri; s[2] = lx * ri;
            } else { s[0] = s[1] = s[2] = 0.f; }

            // A fragments (all 4 q-blocks, hi+lo), one z row set per c
            const int zi = zb + mloc + c - 2;
            const bool vz = (unsigned)zi < 64u;
            const uint32_t jx   = ((uint32_t)zi & 7u) << 4;
            const uint32_t arow = (uint32_t)zi * 128u;
            uint32_t ah[4][4], al[4][4];
#pragma unroll
            for (int q = 0; q < 4; q++) {
                const uint32_t acol = ((uint32_t)(q * 32 + ksub * 16)) ^ jx;
                const uint32_t aH = vz ? (inH + arow + acol) : zeroAddr;
                const uint32_t aL = vz ? (inL + arow + acol) : zeroAddr;
                ldsm4(ah[q][0], ah[q][1], ah[q][2], ah[q][3], aH);
                ldsm4(al[q][0], al[q][1], al[q][2], al[q][3], aL);
            }

            const uint32_t cbase = Bb + (uint32_t)(c * 6 * 2) * 768u + bl_off;
            uint32_t bh0, bh1, bh2, bh3, bl0, bl1, bl2, bl3;

            // ---- blk0: k00 (A q=0 -> acc n-block 0) ----
            ldsm4t(bh0, bh1, bh2, bh3, cbase + 0 * 1536);
            ldsm4t(bl0, bl1, bl2, bl3, cbase + 0 * 1536 + 768);
            mma16816(acc[0], ah[0][0], ah[0][1], ah[0][2], ah[0][3], bh0, bh1);
            mma16816(acc[1], ah[0][0], ah[0][1], ah[0][2], ah[0][3], bh2, bh3);
            mma16816(acc[0], al[0][0], al[0][1], al[0][2], al[0][3], bh0, bh1);
            mma16816(acc[1], al[0][0], al[0][1], al[0][2], al[0][3], bh2, bh3);
            mma16816(acc[0], ah[0][0], ah[0][1], ah[0][2], ah[0][3], bl0, bl1);
            mma16816(acc[1], ah[0][0], ah[0][1], ah[0][2], ah[0][3], bl2, bl3);

            // ---- blk1: k01 rank-1 -> P, then scaled into acc blocks 1..3 ----
            {
                float P[2][4];
#pragma unroll
                for (int j = 0; j < 2; j++)
#pragma unroll
                    for (int r = 0; r < 4; r++) P[j][r] = 0.f;
                ldsm4t(bh0, bh1, bh2, bh3, cbase + 1 * 1536);
                ldsm4t(bl0, bl1, bl2, bl3, cbase + 1 * 1536 + 768);
                mma16816(P[0], ah[0][0], ah[0][1], ah[0][2], ah[0][3], bh0, bh1);
                mma16816(P[1], ah[0][0], ah[0][1], ah[0][2], ah[0][3], bh2, bh3);
                mma16816(P[0], al[0][0], al[0][1], al[0][2], al[0][3], bh0, bh1);
                mma16816(P[1], al[0][0], al[0][1], al[0][2], al[0][3], bh2, bh3);
                mma16816(P[0], ah[0][0], ah[0][1], ah[0][2], ah[0][3], bl0, bl1);
                mma16816(P[1], ah[0][0], ah[0][1], ah[0][2], ah[0][3], bl2, bl3);
#pragma unroll
                for (int k = 0; k < 3; k++) {
                    const float sk = s[k];
#pragma unroll
                    for (int j = 0; j < 2; j++)
#pragma unroll
                        for (int r = 0; r < 4; r++)
                            acc[2 * (k + 1) + j][r] += sk * P[j][r];
                }
            }

            // ---- blk2..4: k10 (A q=i+1 -> acc n-block 0) ----
#pragma unroll
            for (int i = 0; i < 3; i++) {
                ldsm4t(bh0, bh1, bh2, bh3, cbase + (2 + i) * 1536);
                ldsm4t(bl0, bl1, bl2, bl3, cbase + (2 + i) * 1536 + 768);
                const int q = i + 1;
                mma16816(acc[0], ah[q][0], ah[q][1], ah[q][2], ah[q][3], bh0, bh1);
                mma16816(acc[1], ah[q][0], ah[q][1], ah[q][2], ah[q][3], bh2, bh3);
                mma16816(acc[0], al[q][0], al[q][1], al[q][2], al[q][3], bh0, bh1);
                mma16816(acc[1], al[q][0], al[q][1], al[q][2], al[q][3], bh2, bh3);
                mma16816(acc[0], ah[q][0], ah[q][1], ah[q][2], ah[q][3], bl0, bl1);
                mma16816(acc[1], ah[q][0], ah[q][1], ah[q][2], ah[q][3], bl2, bl3);
            }

            // ---- blk5: k11 diagonal, same B for all 3 i ----
            {
                ldsm4t(bh0, bh1, bh2, bh3, cbase + 5 * 1536);
                ldsm4t(bl0, bl1, bl2, bl3, cbase + 5 * 1536 + 768);
#pragma unroll
                for (int k = 0; k < 3; k++) {
                    const int q = k + 1;
                    float* d0 = acc[2 * (k + 1)];
                    float* d1 = acc[2 * (k + 1) + 1];
                    mma16816(d0, ah[q][0], ah[q][1], ah[q][2], ah[q][3], bh0, bh1);
                    mma16816(d1, ah[q][0], ah[q][1], ah[q][2], ah[q][3], bh2, bh3);
                    mma16816(d0, al[q][0], al[q][1], al[q][2], al[q][3], bh0, bh1);
                    mma16816(d1, al[q][0], al[q][1], al[q][2], al[q][3], bh2, bh3);
                    mma16816(d0, ah[q][0], ah[q][1], ah[q][2], ah[q][3], bl0, bl1);
                    mma16816(d1, ah[q][0], ah[q][1], ah[q][2], ah[q][3], bl2, bl3);
                }
            }
        }

        if (p + 1 < npl) CP_WAIT0();
        __syncthreads();
    }

    // ---- epilogue: direct global stores, un-permute cout ----
    const int g  = lane >> 2;
    const int cc = lane & 3;
    const int z  = zb + g;
    const int y  = y0 + ysw;
    float* ob = out + ((((size_t)b * 64) * 64 + x0) * 64 + y) * 64 + z;
#pragma unroll
    for (int nt = 0; nt < 8; nt++) {
        const int n0 = nt * 8 + 2 * cc;
        const int ch0 = (n0 < 16) ? n0 : (16 + 3 * ((n0 - 16) & 15) + ((n0 - 16) >> 4));
        const int n1 = n0 + 1;
        const int ch1 = (n1 < 16) ? n1 : (16 + 3 * ((n1 - 16) & 15) + ((n1 - 16) >> 4));
        float* p0 = ob + (size_t)ch0 * 262144;
        float* p1 = ob + (size_t)ch1 * 262144;
        p0[0] = acc[nt][0];
        p1[0] = acc[nt][1];
        p0[8] = acc[nt][2];
        p1[8] = acc[nt][3];
    }
}

// ---------------------------------------------------------------------------
// Launch
// ---------------------------------------------------------------------------
extern "C" void kernel_launch(void* const* d_in, const int* in_sizes, int n_in,
                              void* d_out, int out_size)
{
    const float* x   = (const float*)d_in[0];
    const float* lw0 = (const float*)d_in[1];
    const float* lw1 = (const float*)d_in[2];
    const float* tp  = (const float*)d_in[3];
    float* out = (float*)d_out;

    xsplit<<<2 * 64 * 64, 256>>>(x);
    build_weights<<<125, 256>>>(lw0, lw1, tp);

    cudaFuncSetAttribute(conv_mma, cudaFuncAttributeMaxDynamicSharedMemorySize,
                         SM_TOT);
    conv_mma<<<2 * 64 * 32, 256, SM_TOT>>>(out);
}